// round 13
// baseline (speedup 1.0000x reference)
#include <cuda_runtime.h>

// u, z: (B=4, C=2048, H=64, W=64) fp32, C = N_T(8) * N_CAPS(16) * CAP_DIM(16)
// v[b,t,c,d,hw] = sum_{kt,kd} w[kt][kd] * u^2[b,(t+kt-1)%8, c, (d+kd-1)%16, hw]
// out = (z + beta) * rsqrt(v + 1e-6)

#define NT   8
#define NC   16
#define CD   16
#define CCH  (NT*NC*CD)        // 2048
#define HWTOT 4096
#define TSTRIDE (NC*CD*HWTOT)  // elements between consecutive t

typedef unsigned long long u64;

__constant__ float c_w[9];     // weights via LDC (uniform port, no L1tex SB slot)

__device__ __forceinline__ u64 fma2(u64 a, u64 b, u64 c) {
    u64 d; asm("fma.rn.f32x2 %0, %1, %2, %3;" : "=l"(d) : "l"(a), "l"(b), "l"(c));
    return d;
}
__device__ __forceinline__ u64 mul2(u64 a, u64 b) {
    u64 d; asm("mul.rn.f32x2 %0, %1, %2;" : "=l"(d) : "l"(a), "l"(b));
    return d;
}
__device__ __forceinline__ u64 add2(u64 a, u64 b) {
    u64 d; asm("add.rn.f32x2 %0, %1, %2;" : "=l"(d) : "l"(a), "l"(b));
    return d;
}
__device__ __forceinline__ u64 pack2(float lo, float hi) {
    u64 r; asm("mov.b64 %0, {%1, %2};" : "=l"(r) : "f"(lo), "f"(hi));
    return r;
}
__device__ __forceinline__ void unpack2(u64 v, float& lo, float& hi) {
    asm("mov.b64 {%0, %1}, %2;" : "=f"(lo), "=f"(hi) : "l"(v));
}
// Read-only 64-bit load with 256B L2 promotion (streaming-friendly).
__device__ __forceinline__ u64 ldg64_nc(const float* p) {
    u64 v; asm("ld.global.nc.L2::256B.b64 %0, [%1];" : "=l"(v) : "l"(p));
    return v;
}
// Streaming (evict-first) 64-bit store: don't pollute L2's u-reuse lines.
__device__ __forceinline__ void stg64_cs(float* p, u64 v) {
    asm volatile("st.global.cs.b64 [%0], %1;" :: "l"(p), "l"(v) : "memory");
}

// No smem, no barriers. lane -> 2 hw (LDG.64), warp -> d, thread does all 8 t.
// Loads front-batched; weights from constant memory; beta via one early LDG.
__global__ __launch_bounds__(256, 3)
void caps_f32x2_kernel(const float* __restrict__ z,
                       const float* __restrict__ u,
                       const float* __restrict__ beta_p,
                       float* __restrict__ out)
{
    const float bts = __ldg(beta_p);           // epilogue-only; hidden

    const int tid  = threadIdx.x;
    const int lane = tid & 31;
    const int warp = tid >> 5;                 // 0..7

    const int bid  = blockIdx.x;               // 8192 total
    const int b    = bid >> 11;                // 2048 blocks per batch
    const int rem  = bid & 2047;
    const int c    = rem >> 7;                 // 128 blocks per capsule
    const int rem2 = rem & 127;
    const int dg   = rem2 >> 6;                // d-half: 0 or 1
    const int tile = rem2 & 63;                // hw tile (64 hw each)
    const int hw0  = tile * 64;

    const int d  = dg * 8 + warp;              // 0..15
    const int dm = (d + CD - 1) & (CD - 1);
    const int dp = (d + 1) & (CD - 1);

    const int baseB = b * (CCH * HWTOT);
    const int cOff  = c * CD;
    const int hwoff = hw0 + lane * 2;

    const float* ub = u + baseB + hwoff;
    const float* zb = z + baseB + hwoff;

    const int chm = (cOff + dm) * HWTOT;
    const int ch0 = (cOff + d ) * HWTOT;
    const int chp = (cOff + dp) * HWTOT;

    // ---- load burst: 24 u + 8 z LDG.64, all independent, front-batched ----
    u64 am[NT], a0[NT], ap[NT], zv[NT];
    #pragma unroll
    for (int t = 0; t < NT; ++t) {
        const int toff = t * TSTRIDE;
        am[t] = ldg64_nc(ub + toff + chm);
        a0[t] = ldg64_nc(ub + toff + ch0);
        ap[t] = ldg64_nc(ub + toff + chp);
    }
    #pragma unroll
    for (int t = 0; t < NT; ++t)
        zv[t] = ldg64_nc(zb + t * TSTRIDE + ch0);

    const u64 w00 = pack2(c_w[0], c_w[0]), w01 = pack2(c_w[1], c_w[1]), w02 = pack2(c_w[2], c_w[2]);
    const u64 w10 = pack2(c_w[3], c_w[3]), w11 = pack2(c_w[4], c_w[4]), w12 = pack2(c_w[5], c_w[5]);
    const u64 w20 = pack2(c_w[6], c_w[6]), w21 = pack2(c_w[7], c_w[7]), w22 = pack2(c_w[8], c_w[8]);
    const u64 betap = pack2(bts, bts);
    const u64 epsp  = pack2(1e-6f, 1e-6f);

    u64 v[NT];
    #pragma unroll
    for (int t = 0; t < NT; ++t) v[t] = 0ull;

    // Source row s scatters into outputs s+1 (w row 0), s (row 1), s-1 (row 2).
    #pragma unroll
    for (int s = 0; s < NT; ++s) {
        const u64 sm = mul2(am[s], am[s]);
        const u64 s0 = mul2(a0[s], a0[s]);
        const u64 sp = mul2(ap[s], ap[s]);
        const int tn = (s + 1) & (NT - 1);
        const int tb = (s + NT - 1) & (NT - 1);
        v[tn] = fma2(w00, sm, fma2(w01, s0, fma2(w02, sp, v[tn])));
        v[s]  = fma2(w10, sm, fma2(w11, s0, fma2(w12, sp, v[s])));
        v[tb] = fma2(w20, sm, fma2(w21, s0, fma2(w22, sp, v[tb])));
    }

    float* ob = out + baseB + hwoff;
    #pragma unroll
    for (int t = 0; t < NT; ++t) {
        const u64 vz = add2(zv[t], betap);
        const u64 vv = add2(v[t], epsp);
        float vlo, vhi;
        unpack2(vv, vlo, vhi);
        const u64 r = pack2(__frsqrt_rn(vlo), __frsqrt_rn(vhi));
        const u64 o = mul2(vz, r);
        stg64_cs(ob + t * TSTRIDE + ch0, o);
    }
}

extern "C" void kernel_launch(void* const* d_in, const int* in_sizes, int n_in,
                              void* d_out, int out_size)
{
    const float* z    = (const float*)d_in[0];
    const float* u    = (const float*)d_in[1];
    const float* beta = (const float*)d_in[3];   // 1 float
    float* out        = (float*)d_out;

    // Weights (9 floats) -> constant memory: single D2D memcpy node.
    cudaMemcpyToSymbolAsync(c_w, d_in[2], 9 * sizeof(float), 0,
                            cudaMemcpyDeviceToDevice);

    const int B    = in_sizes[0] / (CCH * HWTOT);     // 4
    const int grid = B * NC * 2 * 64;                 // 8192 blocks

    caps_f32x2_kernel<<<grid, 256>>>(z, u, beta, out);
}

// round 14
// speedup vs baseline: 1.0038x; 1.0038x over previous
#include <cuda_runtime.h>

// u, z: (B=4, C=2048, H=64, W=64) fp32, C = N_T(8) * N_CAPS(16) * CAP_DIM(16)
// v[b,t,c,d,hw] = sum_{kt,kd} w[kt][kd] * u^2[b,(t+kt-1)%8, c, (d+kd-1)%16, hw]
// out = (z + beta) * rsqrt(v + 1e-6)

#define NT   8
#define NC   16
#define CD   16
#define CCH  (NT*NC*CD)        // 2048
#define HWTOT 4096
#define TSTRIDE (NC*CD*HWTOT)  // elements between consecutive t

typedef unsigned long long u64;

__constant__ float c_w[9];     // weights via LDC (uniform port, no L1tex SB slot)

__device__ __forceinline__ u64 fma2(u64 a, u64 b, u64 c) {
    u64 d; asm("fma.rn.f32x2 %0, %1, %2, %3;" : "=l"(d) : "l"(a), "l"(b), "l"(c));
    return d;
}
__device__ __forceinline__ u64 mul2(u64 a, u64 b) {
    u64 d; asm("mul.rn.f32x2 %0, %1, %2;" : "=l"(d) : "l"(a), "l"(b));
    return d;
}
__device__ __forceinline__ u64 add2(u64 a, u64 b) {
    u64 d; asm("add.rn.f32x2 %0, %1, %2;" : "=l"(d) : "l"(a), "l"(b));
    return d;
}
__device__ __forceinline__ u64 pack2(float lo, float hi) {
    u64 r; asm("mov.b64 %0, {%1, %2};" : "=l"(r) : "f"(lo), "f"(hi));
    return r;
}
__device__ __forceinline__ void unpack2(u64 v, float& lo, float& hi) {
    asm("mov.b64 {%0, %1}, %2;" : "=f"(lo), "=f"(hi) : "l"(v));
}
// Read-only 64-bit load with 256B L2 promotion.
__device__ __forceinline__ u64 ldg64_nc(const float* p) {
    u64 v; asm("ld.global.nc.L2::256B.b64 %0, [%1];" : "=l"(v) : "l"(p));
    return v;
}

// No smem, no barriers. lane -> 2 hw (LDG.64), warp -> d, thread does all 8 t.
// Loads front-batched (MLP); weights via constant memory; beta via one early
// LDG (epilogue-only dependency, fully hidden behind the burst).
__global__ __launch_bounds__(256, 3)
void caps_f32x2_kernel(const float* __restrict__ z,
                       const float* __restrict__ u,
                       const float* __restrict__ beta_p,
                       float* __restrict__ out)
{
    const float bts = __ldg(beta_p);           // epilogue-only; hidden

    const int tid  = threadIdx.x;
    const int lane = tid & 31;
    const int warp = tid >> 5;                 // 0..7

    const int bid  = blockIdx.x;               // 8192 total
    const int b    = bid >> 11;                // 2048 blocks per batch
    const int rem  = bid & 2047;
    const int c    = rem >> 7;                 // 128 blocks per capsule
    const int rem2 = rem & 127;
    const int dg   = rem2 >> 6;                // d-half: 0 or 1
    const int tile = rem2 & 63;                // hw tile (64 hw each)
    const int hw0  = tile * 64;

    const int d  = dg * 8 + warp;              // 0..15
    const int dm = (d + CD - 1) & (CD - 1);
    const int dp = (d + 1) & (CD - 1);

    const int baseB = b * (CCH * HWTOT);
    const int cOff  = c * CD;
    const int hwoff = hw0 + lane * 2;

    const float* ub = u + baseB + hwoff;
    const float* zb = z + baseB + hwoff;

    const int chm = (cOff + dm) * HWTOT;
    const int ch0 = (cOff + d ) * HWTOT;
    const int chp = (cOff + dp) * HWTOT;

    // ---- load burst: 24 u + 8 z LDG.64, all independent, front-batched ----
    u64 am[NT], a0[NT], ap[NT], zv[NT];
    #pragma unroll
    for (int t = 0; t < NT; ++t) {
        const int toff = t * TSTRIDE;
        am[t] = ldg64_nc(ub + toff + chm);
        a0[t] = ldg64_nc(ub + toff + ch0);
        ap[t] = ldg64_nc(ub + toff + chp);
    }
    #pragma unroll
    for (int t = 0; t < NT; ++t)
        zv[t] = ldg64_nc(zb + t * TSTRIDE + ch0);

    const u64 w00 = pack2(c_w[0], c_w[0]), w01 = pack2(c_w[1], c_w[1]), w02 = pack2(c_w[2], c_w[2]);
    const u64 w10 = pack2(c_w[3], c_w[3]), w11 = pack2(c_w[4], c_w[4]), w12 = pack2(c_w[5], c_w[5]);
    const u64 w20 = pack2(c_w[6], c_w[6]), w21 = pack2(c_w[7], c_w[7]), w22 = pack2(c_w[8], c_w[8]);
    const u64 betap = pack2(bts, bts);
    const u64 epsp  = pack2(1e-6f, 1e-6f);

    u64 v[NT];
    #pragma unroll
    for (int t = 0; t < NT; ++t) v[t] = 0ull;

    // Source row s scatters into outputs s+1 (w row 0), s (row 1), s-1 (row 2).
    #pragma unroll
    for (int s = 0; s < NT; ++s) {
        const u64 sm = mul2(am[s], am[s]);
        const u64 s0 = mul2(a0[s], a0[s]);
        const u64 sp = mul2(ap[s], ap[s]);
        const int tn = (s + 1) & (NT - 1);
        const int tb = (s + NT - 1) & (NT - 1);
        v[tn] = fma2(w00, sm, fma2(w01, s0, fma2(w02, sp, v[tn])));
        v[s]  = fma2(w10, sm, fma2(w11, s0, fma2(w12, sp, v[s])));
        v[tb] = fma2(w20, sm, fma2(w21, s0, fma2(w22, sp, v[tb])));
    }

    float* ob = out + baseB + hwoff;
    #pragma unroll
    for (int t = 0; t < NT; ++t) {
        const u64 vz = add2(zv[t], betap);
        const u64 vv = add2(v[t], epsp);
        float vlo, vhi;
        unpack2(vv, vlo, vhi);
        const u64 r = pack2(__frsqrt_rn(vlo), __frsqrt_rn(vhi));
        const u64 o = mul2(vz, r);
        *reinterpret_cast<u64*>(ob + t * TSTRIDE + ch0) = o;
    }
}

extern "C" void kernel_launch(void* const* d_in, const int* in_sizes, int n_in,
                              void* d_out, int out_size)
{
    const float* z    = (const float*)d_in[0];
    const float* u    = (const float*)d_in[1];
    const float* beta = (const float*)d_in[3];   // 1 float
    float* out        = (float*)d_out;

    // Weights (9 floats) -> constant memory: single D2D memcpy node.
    cudaMemcpyToSymbolAsync(c_w, d_in[2], 9 * sizeof(float), 0,
                            cudaMemcpyDeviceToDevice);

    const int B    = in_sizes[0] / (CCH * HWTOT);     // 4
    const int grid = B * NC * 2 * 64;                 // 8192 blocks

    caps_f32x2_kernel<<<grid, 256>>>(z, u, beta, out);
}